// round 4
// baseline (speedup 1.0000x reference)
#include <cuda_runtime.h>

#define N_NODES 100000
#define N_EDGES 1600000
#define IN_F    128
#define HID     64
#define N_CLS   4
#define BN_EPS  1e-5f

#define SCAN_BS   512
#define SCAN_NB   ((N_NODES + SCAN_BS - 1) / SCAN_BS)   // 196

// ------------------------- device scratch (no allocs allowed) ---------------
__device__ __align__(256) int   g_srcA[N_EDGES];
__device__ __align__(256) int   g_dstA[N_EDGES];
__device__ __align__(256) int   g_cnt[N_NODES];
__device__ __align__(256) int   g_off[N_NODES + 1];
__device__ __align__(256) int   g_cur[N_NODES];
__device__ __align__(256) int   g_bsum[SCAN_NB];
__device__ __align__(256) int   g_csr_src[N_EDGES];
__device__ __align__(256) float g_csr_coef[N_EDGES];
__device__ __align__(256) float g_dinv[N_NODES];
__device__ __align__(256) float g_bufA[N_NODES * HID];      // 25.6 MB
__device__ __align__(256) float g_bufB[N_NODES * HID];      // 25.6 MB
__device__ __align__(256) float g_stats[2 * HID];

// ------------------------- graph prep ----------------------------------------
__global__ void k_zero_cnt() {
    int i = blockIdx.x * blockDim.x + threadIdx.x;
    if (i < N_NODES) g_cnt[i] = 0;
}

// edge_index is int32 (JAX default: int64 request silently becomes int32).
__global__ void k_count(const int* __restrict__ ei) {
    int e = blockIdx.x * blockDim.x + threadIdx.x;
    if (e >= N_EDGES) return;
    int s = ei[e];
    int d = ei[N_EDGES + e];
    if ((unsigned)s >= N_NODES) s = 0;   // defensive: never trap
    if ((unsigned)d >= N_NODES) d = 0;
    g_srcA[e] = s;
    g_dstA[e] = d;
    atomicAdd(&g_cnt[d], 1);
}

__global__ void k_dinv() {
    int i = blockIdx.x * blockDim.x + threadIdx.x;
    if (i < N_NODES) g_dinv[i] = rsqrtf((float)(g_cnt[i] + 1));  // +1 self-loop
}

// exclusive scan of g_cnt -> g_off, 3 stages
__global__ void k_scan1() {
    __shared__ int sh[SCAN_BS];
    int t = threadIdx.x;
    int i = blockIdx.x * SCAN_BS + t;
    int v = (i < N_NODES) ? g_cnt[i] : 0;
    sh[t] = v;
    __syncthreads();
    for (int o = 1; o < SCAN_BS; o <<= 1) {
        int x = (t >= o) ? sh[t - o] : 0;
        __syncthreads();
        sh[t] += x;
        __syncthreads();
    }
    if (i < N_NODES) g_off[i] = sh[t] - v;          // exclusive within block
    if (t == SCAN_BS - 1) g_bsum[blockIdx.x] = sh[t];
}

__global__ void k_scan2() {
    __shared__ int sh[256];
    int t = threadIdx.x;
    int v = (t < SCAN_NB) ? g_bsum[t] : 0;
    sh[t] = v;
    __syncthreads();
    for (int o = 1; o < 256; o <<= 1) {
        int x = (t >= o) ? sh[t - o] : 0;
        __syncthreads();
        sh[t] += x;
        __syncthreads();
    }
    if (t < SCAN_NB) g_bsum[t] = sh[t] - v;         // exclusive
}

__global__ void k_scan3() {
    int i = blockIdx.x * blockDim.x + threadIdx.x;
    if (i == 0) g_off[N_NODES] = N_EDGES;
    if (i >= N_NODES) return;
    int o = g_off[i] + g_bsum[i / SCAN_BS];
    g_off[i] = o;
    g_cur[i] = o;
}

__global__ void k_fill() {
    int e = blockIdx.x * blockDim.x + threadIdx.x;
    if (e >= N_EDGES) return;
    int s = g_srcA[e], d = g_dstA[e];
    int slot = atomicAdd(&g_cur[d], 1);
    if ((unsigned)slot >= N_EDGES) return;          // defensive
    g_csr_src[slot]  = s;
    g_csr_coef[slot] = g_dinv[s] * g_dinv[d];
}

// ------------------------- GEMM: [N, K] x [K, 64] -----------------------------
// Block: 256 threads, 32 rows per block. 100000 = 3125 * 32 exactly.
template <int K>
__global__ void k_gemm_n64(const float* __restrict__ X, const float* __restrict__ W,
                           float* __restrict__ T) {
    __shared__ float sW[K * 64];
    __shared__ float sX[32 * K];
    const int tid = threadIdx.x;

    for (int i = tid * 4; i < K * 64; i += 256 * 4)
        *(float4*)&sW[i] = *(const float4*)&W[i];

    const int row0 = blockIdx.x * 32;
    for (int i = tid * 4; i < 32 * K; i += 256 * 4) {
        int r = i / K, k = i % K;
        *(float4*)&sX[i] = *(const float4*)&X[(row0 + r) * K + k];
    }
    __syncthreads();

    const int r  = tid >> 3;        // 0..31
    const int c0 = (tid & 7) * 8;   // 0..56
    float acc[8];
#pragma unroll
    for (int c = 0; c < 8; c++) acc[c] = 0.0f;

    const float* xr = &sX[r * K];
    for (int k = 0; k < K; k += 4) {
        float4 xv = *(const float4*)&xr[k];
        float xs[4] = {xv.x, xv.y, xv.z, xv.w};
#pragma unroll
        for (int kk = 0; kk < 4; kk++) {
            float4 w0 = *(const float4*)&sW[(k + kk) * 64 + c0];
            float4 w1 = *(const float4*)&sW[(k + kk) * 64 + c0 + 4];
            acc[0] += xs[kk] * w0.x; acc[1] += xs[kk] * w0.y;
            acc[2] += xs[kk] * w0.z; acc[3] += xs[kk] * w0.w;
            acc[4] += xs[kk] * w1.x; acc[5] += xs[kk] * w1.y;
            acc[6] += xs[kk] * w1.z; acc[7] += xs[kk] * w1.w;
        }
    }
    float* o = &T[(row0 + r) * 64 + c0];
    *(float4*)o       = make_float4(acc[0], acc[1], acc[2], acc[3]);
    *(float4*)(o + 4) = make_float4(acc[4], acc[5], acc[6], acc[7]);
}

// ------------------------- GEMM: [N, 64] x [64, 4] ----------------------------
__global__ void k_gemm_n4(const float* __restrict__ H, const float* __restrict__ W,
                          float* __restrict__ T) {
    __shared__ float sH[64 * 65];
    __shared__ float sW[64 * 4];
    const int tid = threadIdx.x;
    sW[tid] = W[tid];   // 256 elems exactly
    const int row0 = blockIdx.x * 64;
    for (int i = tid; i < 64 * 64; i += 256) {
        int r = i >> 6, k = i & 63;
        sH[r * 65 + k] = (row0 + r < N_NODES) ? H[(row0 + r) * 64 + k] : 0.0f;
    }
    __syncthreads();
    const int r = tid >> 2, c = tid & 3;
    float acc = 0.0f;
#pragma unroll 8
    for (int k = 0; k < 64; k++)
        acc += sH[r * 65 + k] * sW[k * 4 + c];
    if (row0 + r < N_NODES) T[(row0 + r) * 4 + c] = acc;
}

// ------------------------- aggregation (gather, HID=64) -----------------------
// 16 threads per node, each owning 4 contiguous columns.
__global__ void k_gather64(const float* __restrict__ T, const float* __restrict__ b,
                           float* __restrict__ A) {
    int gid = blockIdx.x * blockDim.x + threadIdx.x;
    if (blockIdx.x == 0 && threadIdx.x < 2 * HID) g_stats[threadIdx.x] = 0.0f;
    int node = gid >> 4;
    if (node >= N_NODES) return;
    int c = (gid & 15) * 4;

    const int beg = g_off[node];
    const int end = g_off[node + 1];

    float dv = g_dinv[node];
    float sc = dv * dv;
    float4 bb = *(const float4*)&b[c];
    float4 t  = *(const float4*)&T[node * 64 + c];
    float4 acc;
    acc.x = t.x * sc + bb.x; acc.y = t.y * sc + bb.y;
    acc.z = t.z * sc + bb.z; acc.w = t.w * sc + bb.w;

    for (int j = beg; j < end; j++) {
        int   s  = g_csr_src[j];
        float cf = g_csr_coef[j];
        float4 v = *(const float4*)&T[s * 64 + c];
        acc.x += v.x * cf; acc.y += v.y * cf;
        acc.z += v.z * cf; acc.w += v.w * cf;
    }
    *(float4*)&A[node * 64 + c] = acc;
}

// ------------------------- aggregation (gather, N_CLS=4) ----------------------
__global__ void k_gather4(const float* __restrict__ T, const float* __restrict__ b,
                          float* __restrict__ O) {
    int node = blockIdx.x * blockDim.x + threadIdx.x;
    if (node >= N_NODES) return;
    float dv = g_dinv[node];
    float sc = dv * dv;
    float4 t = *(const float4*)&T[node * 4];
    float4 acc;
    acc.x = t.x * sc + b[0]; acc.y = t.y * sc + b[1];
    acc.z = t.z * sc + b[2]; acc.w = t.w * sc + b[3];
    int beg = g_off[node], end = g_off[node + 1];
    for (int j = beg; j < end; j++) {
        int   s  = g_csr_src[j];
        float cf = g_csr_coef[j];
        float4 v = *(const float4*)&T[s * 4];
        acc.x += v.x * cf; acc.y += v.y * cf;
        acc.z += v.z * cf; acc.w += v.w * cf;
    }
    *(float4*)&O[node * 4] = acc;
}

// ------------------------- batchnorm -----------------------------------------
__global__ void k_bn_stats(const float* __restrict__ A) {
    int col = threadIdx.x & 63;
    int rl  = threadIdx.x >> 6;   // 0..3
    float s = 0.0f, q = 0.0f;
    for (int r = blockIdx.x * 4 + rl; r < N_NODES; r += gridDim.x * 4) {
        float v = A[r * 64 + col];
        s += v; q += v * v;
    }
    __shared__ float sh[512];
    sh[threadIdx.x]       = s;
    sh[256 + threadIdx.x] = q;
    __syncthreads();
    if (rl == 0) {
        s = sh[col] + sh[64 + col] + sh[128 + col] + sh[192 + col];
        q = sh[256 + col] + sh[320 + col] + sh[384 + col] + sh[448 + col];
        atomicAdd(&g_stats[col], s);
        atomicAdd(&g_stats[64 + col], q);
    }
}

__global__ void k_bn_apply_relu(float* __restrict__ A, const float* __restrict__ g,
                                const float* __restrict__ be) {
    int idx = blockIdx.x * blockDim.x + threadIdx.x;
    if (idx >= N_NODES * 16) return;
    int c = (idx & 15) * 4;
    const float invN = 1.0f / (float)N_NODES;
    float4 a = *(float4*)&A[idx * 4];
    float4 o;
#pragma unroll
    for (int j = 0; j < 4; j++) {
        int ci = c + j;
        float m  = g_stats[ci] * invN;
        float vv = g_stats[64 + ci] * invN - m * m;
        float rs = rsqrtf(vv + BN_EPS);
        float av = (&a.x)[j];
        float val = (av - m) * rs * g[ci] + be[ci];
        (&o.x)[j] = fmaxf(val, 0.0f);
    }
    *(float4*)&A[idx * 4] = o;
}

// ------------------------- launch --------------------------------------------
extern "C" void kernel_launch(void* const* d_in, const int* in_sizes, int n_in,
                              void* d_out, int out_size) {
    const float* x   = (const float*)d_in[0];
    const int*   ei  = (const int*)d_in[1];      // int32 (JAX default int)
    const float* W1  = (const float*)d_in[2];
    const float* b1  = (const float*)d_in[3];
    const float* g1  = (const float*)d_in[4];
    const float* be1 = (const float*)d_in[5];
    const float* W2  = (const float*)d_in[6];
    const float* b2  = (const float*)d_in[7];
    const float* g2  = (const float*)d_in[8];
    const float* be2 = (const float*)d_in[9];
    const float* W3  = (const float*)d_in[10];
    const float* b3  = (const float*)d_in[11];
    float* out = (float*)d_out;

    float *bufA, *bufB;
    cudaGetSymbolAddress((void**)&bufA, g_bufA);
    cudaGetSymbolAddress((void**)&bufB, g_bufB);

    const int TB = 256;
    const int gN   = (N_NODES + TB - 1) / TB;          // 391
    const int gE   = (N_EDGES + TB - 1) / TB;          // 6250
    const int gNE  = (N_NODES * 16 + TB - 1) / TB;     // 6250
    const int gM32 = N_NODES / 32;                     // 3125
    const int gM64 = (N_NODES + 63) / 64;              // 1563

    // graph prep: degrees, dinv, CSR build
    k_zero_cnt<<<gN, TB>>>();
    k_count<<<gE, TB>>>(ei);
    k_dinv<<<gN, TB>>>();
    k_scan1<<<SCAN_NB, SCAN_BS>>>();
    k_scan2<<<1, 256>>>();
    k_scan3<<<gN, TB>>>();
    k_fill<<<gE, TB>>>();

    // layer 1: t1 = x @ W1 -> A ; gather-aggregate -> B ; BN+ReLU in place on B
    k_gemm_n64<IN_F><<<gM32, TB>>>(x, W1, bufA);
    k_gather64<<<gNE, TB>>>(bufA, b1, bufB);
    k_bn_stats<<<512, TB>>>(bufB);
    k_bn_apply_relu<<<gNE, TB>>>(bufB, g1, be1);

    // layer 2
    k_gemm_n64<HID><<<gM32, TB>>>(bufB, W2, bufA);
    k_gather64<<<gNE, TB>>>(bufA, b2, bufB);
    k_bn_stats<<<512, TB>>>(bufB);
    k_bn_apply_relu<<<gNE, TB>>>(bufB, g2, be2);

    // layer 3
    k_gemm_n4<<<gM64, TB>>>(bufB, W3, bufA);
    k_gather4<<<gN, TB>>>(bufA, b3, out);
}

// round 5
// speedup vs baseline: 1.0241x; 1.0241x over previous
#include <cuda_runtime.h>

#define N_NODES 100000
#define N_EDGES 1600000
#define IN_F    128
#define HID     64
#define N_CLS   4
#define BN_EPS  1e-5f

#define SCAN_BS   512
#define SCAN_NB   ((N_NODES + SCAN_BS - 1) / SCAN_BS)   // 196
#define NGROUPS   (N_NODES / 16)                        // 6250 exactly
#define GATHER_GRID 2000

// ------------------------- device scratch (no allocs allowed) ---------------
__device__ __align__(256) int   g_cnt[N_NODES];
__device__ __align__(256) int   g_off[N_NODES + 1];
__device__ __align__(256) int   g_cur[N_NODES];
__device__ __align__(256) int   g_bsum[SCAN_NB];
__device__ __align__(256) int2  g_edge[N_EDGES];            // {src, coef bits}
__device__ __align__(256) float g_dinv[N_NODES];
__device__ __align__(256) float g_bufA[N_NODES * HID];      // 25.6 MB
__device__ __align__(256) float g_bufB[N_NODES * HID];      // 25.6 MB
__device__ __align__(256) float g_stats1[2 * HID];
__device__ __align__(256) float g_stats2[2 * HID];

// ------------------------- graph prep ----------------------------------------
__global__ void k_zero_cnt() {
    int i = blockIdx.x * blockDim.x + threadIdx.x;
    if (i < N_NODES) g_cnt[i] = 0;
    if (i < 2 * HID) { g_stats1[i] = 0.0f; g_stats2[i] = 0.0f; }
}

// edge_index is int32 (JAX default: int64 request silently becomes int32).
__global__ void k_count(const int* __restrict__ ei) {
    int e = blockIdx.x * blockDim.x + threadIdx.x;
    if (e >= N_EDGES) return;
    int d = ei[N_EDGES + e];
    if ((unsigned)d >= N_NODES) d = 0;
    atomicAdd(&g_cnt[d], 1);
}

__global__ void k_dinv() {
    int i = blockIdx.x * blockDim.x + threadIdx.x;
    if (i < N_NODES) g_dinv[i] = rsqrtf((float)(g_cnt[i] + 1));  // +1 self-loop
}

// exclusive scan of g_cnt -> g_off, 3 stages
__global__ void k_scan1() {
    __shared__ int sh[SCAN_BS];
    int t = threadIdx.x;
    int i = blockIdx.x * SCAN_BS + t;
    int v = (i < N_NODES) ? g_cnt[i] : 0;
    sh[t] = v;
    __syncthreads();
    for (int o = 1; o < SCAN_BS; o <<= 1) {
        int x = (t >= o) ? sh[t - o] : 0;
        __syncthreads();
        sh[t] += x;
        __syncthreads();
    }
    if (i < N_NODES) g_off[i] = sh[t] - v;          // exclusive within block
    if (t == SCAN_BS - 1) g_bsum[blockIdx.x] = sh[t];
}

__global__ void k_scan2() {
    __shared__ int sh[256];
    int t = threadIdx.x;
    int v = (t < SCAN_NB) ? g_bsum[t] : 0;
    sh[t] = v;
    __syncthreads();
    for (int o = 1; o < 256; o <<= 1) {
        int x = (t >= o) ? sh[t - o] : 0;
        __syncthreads();
        sh[t] += x;
        __syncthreads();
    }
    if (t < SCAN_NB) g_bsum[t] = sh[t] - v;         // exclusive
}

__global__ void k_scan3() {
    int i = blockIdx.x * blockDim.x + threadIdx.x;
    if (i == 0) g_off[N_NODES] = N_EDGES;
    if (i >= N_NODES) return;
    int o = g_off[i] + g_bsum[i / SCAN_BS];
    g_off[i] = o;
    g_cur[i] = o;
}

__global__ void k_fill(const int* __restrict__ ei) {
    int e = blockIdx.x * blockDim.x + threadIdx.x;
    if (e >= N_EDGES) return;
    int s = ei[e];
    int d = ei[N_EDGES + e];
    if ((unsigned)s >= N_NODES) s = 0;
    if ((unsigned)d >= N_NODES) d = 0;
    int slot = atomicAdd(&g_cur[d], 1);
    if ((unsigned)slot >= N_EDGES) return;          // defensive
    float cf = g_dinv[s] * g_dinv[d];
    g_edge[slot] = make_int2(s, __float_as_int(cf));
}

// ------------------------- GEMM: [N, K] x [K, 64] -----------------------------
// Block: 256 threads, 32 rows per block. 100000 = 3125 * 32 exactly.
// AFF: apply per-column BN affine + ReLU to X while staging (column k of X).
template <int K, bool AFF>
__global__ void k_gemm_n64(const float* __restrict__ X, const float* __restrict__ W,
                           float* __restrict__ T, const float* __restrict__ stats,
                           const float* __restrict__ gam, const float* __restrict__ bet) {
    __shared__ float sW[K * 64];
    __shared__ float sX[32 * K];
    __shared__ float sa[AFF ? K : 1];
    __shared__ float sd[AFF ? K : 1];
    const int tid = threadIdx.x;

    for (int i = tid * 4; i < K * 64; i += 256 * 4)
        *(float4*)&sW[i] = *(const float4*)&W[i];

    if (AFF && tid < K) {
        const float invN = 1.0f / (float)N_NODES;
        float m  = stats[tid] * invN;
        float vv = stats[HID + tid] * invN - m * m;
        float rs = rsqrtf(vv + BN_EPS);
        float a  = rs * gam[tid];
        sa[tid] = a;
        sd[tid] = bet[tid] - m * a;
    }
    if (AFF) __syncthreads();

    const int row0 = blockIdx.x * 32;
    for (int i = tid * 4; i < 32 * K; i += 256 * 4) {
        int r = i / K, k = i % K;
        float4 v = *(const float4*)&X[(row0 + r) * K + k];
        if (AFF) {
            v.x = fmaxf(v.x * sa[k]     + sd[k],     0.0f);
            v.y = fmaxf(v.y * sa[k + 1] + sd[k + 1], 0.0f);
            v.z = fmaxf(v.z * sa[k + 2] + sd[k + 2], 0.0f);
            v.w = fmaxf(v.w * sa[k + 3] + sd[k + 3], 0.0f);
        }
        *(float4*)&sX[i] = v;
    }
    __syncthreads();

    const int r  = tid >> 3;        // 0..31
    const int c0 = (tid & 7) * 8;   // 0..56
    float acc[8];
#pragma unroll
    for (int c = 0; c < 8; c++) acc[c] = 0.0f;

    const float* xr = &sX[r * K];
    for (int k = 0; k < K; k += 4) {
        float4 xv = *(const float4*)&xr[k];
        float xs[4] = {xv.x, xv.y, xv.z, xv.w};
#pragma unroll
        for (int kk = 0; kk < 4; kk++) {
            float4 w0 = *(const float4*)&sW[(k + kk) * 64 + c0];
            float4 w1 = *(const float4*)&sW[(k + kk) * 64 + c0 + 4];
            acc[0] += xs[kk] * w0.x; acc[1] += xs[kk] * w0.y;
            acc[2] += xs[kk] * w0.z; acc[3] += xs[kk] * w0.w;
            acc[4] += xs[kk] * w1.x; acc[5] += xs[kk] * w1.y;
            acc[6] += xs[kk] * w1.z; acc[7] += xs[kk] * w1.w;
        }
    }
    float* o = &T[(row0 + r) * 64 + c0];
    *(float4*)o       = make_float4(acc[0], acc[1], acc[2], acc[3]);
    *(float4*)(o + 4) = make_float4(acc[4], acc[5], acc[6], acc[7]);
}

// ------------------------- GEMM: [N, 64] x [64, 4], BN2 affine fused ----------
__global__ void k_gemm_n4(const float* __restrict__ H, const float* __restrict__ W,
                          float* __restrict__ T, const float* __restrict__ stats,
                          const float* __restrict__ gam, const float* __restrict__ bet) {
    __shared__ float sH[64 * 65];
    __shared__ float sW[64 * 4];
    __shared__ float sa[64], sd[64];
    const int tid = threadIdx.x;
    sW[tid] = W[tid];   // 256 elems exactly
    if (tid < 64) {
        const float invN = 1.0f / (float)N_NODES;
        float m  = stats[tid] * invN;
        float vv = stats[HID + tid] * invN - m * m;
        float rs = rsqrtf(vv + BN_EPS);
        float a  = rs * gam[tid];
        sa[tid] = a;
        sd[tid] = bet[tid] - m * a;
    }
    __syncthreads();
    const int row0 = blockIdx.x * 64;
    for (int i = tid; i < 64 * 64; i += 256) {
        int r = i >> 6, k = i & 63;
        float v = 0.0f;
        if (row0 + r < N_NODES) {
            v = H[(row0 + r) * 64 + k];
            v = fmaxf(v * sa[k] + sd[k], 0.0f);
        }
        sH[r * 65 + k] = v;
    }
    __syncthreads();
    const int r = tid >> 2, c = tid & 3;
    float acc = 0.0f;
#pragma unroll 8
    for (int k = 0; k < 64; k++)
        acc += sH[r * 65 + k] * sW[k * 4 + c];
    if (row0 + r < N_NODES) T[(row0 + r) * 4 + c] = acc;
}

// ------------------------- aggregation (gather, HID=64) + fused BN stats ------
// 16 threads per node, each owning 4 contiguous columns; grid-strided groups.
__global__ void k_gather64(const float* __restrict__ T, const float* __restrict__ b,
                           float* __restrict__ A, float* __restrict__ stats) {
    const int tid = threadIdx.x;
    const int sub = tid >> 4;       // node-in-group 0..15
    const int c   = (tid & 15) * 4; // column group
    const float4 bb = *(const float4*)&b[c];

    float s0 = 0, s1 = 0, s2 = 0, s3 = 0;
    float q0 = 0, q1 = 0, q2 = 0, q3 = 0;

    for (int grp = blockIdx.x; grp < NGROUPS; grp += gridDim.x) {
        const int node = grp * 16 + sub;
        const int beg = g_off[node];
        const int end = g_off[node + 1];
        const float dv = g_dinv[node];
        const float sc = dv * dv;
        float4 t = *(const float4*)&T[node * 64 + c];
        float4 acc;
        acc.x = t.x * sc + bb.x; acc.y = t.y * sc + bb.y;
        acc.z = t.z * sc + bb.z; acc.w = t.w * sc + bb.w;

        for (int j = beg; j < end; j++) {
            int2  e  = g_edge[j];
            float cf = __int_as_float(e.y);
            float4 v = *(const float4*)&T[e.x * 64 + c];
            acc.x += v.x * cf; acc.y += v.y * cf;
            acc.z += v.z * cf; acc.w += v.w * cf;
        }
        *(float4*)&A[node * 64 + c] = acc;

        s0 += acc.x; q0 += acc.x * acc.x;
        s1 += acc.y; q1 += acc.y * acc.y;
        s2 += acc.z; q2 += acc.z * acc.z;
        s3 += acc.w; q3 += acc.w * acc.w;
    }

    __shared__ float ssum[64], ssq[64];
    if (tid < 64) { ssum[tid] = 0.0f; ssq[tid] = 0.0f; }
    __syncthreads();
    atomicAdd(&ssum[c],     s0); atomicAdd(&ssq[c],     q0);
    atomicAdd(&ssum[c + 1], s1); atomicAdd(&ssq[c + 1], q1);
    atomicAdd(&ssum[c + 2], s2); atomicAdd(&ssq[c + 2], q2);
    atomicAdd(&ssum[c + 3], s3); atomicAdd(&ssq[c + 3], q3);
    __syncthreads();
    if (tid < 64) {
        atomicAdd(&stats[tid],       ssum[tid]);
        atomicAdd(&stats[HID + tid], ssq[tid]);
    }
}

// ------------------------- aggregation (gather, N_CLS=4) ----------------------
__global__ void k_gather4(const float* __restrict__ T, const float* __restrict__ b,
                          float* __restrict__ O) {
    int node = blockIdx.x * blockDim.x + threadIdx.x;
    if (node >= N_NODES) return;
    float dv = g_dinv[node];
    float sc = dv * dv;
    float4 t = *(const float4*)&T[node * 4];
    float4 acc;
    acc.x = t.x * sc + b[0]; acc.y = t.y * sc + b[1];
    acc.z = t.z * sc + b[2]; acc.w = t.w * sc + b[3];
    int beg = g_off[node], end = g_off[node + 1];
    for (int j = beg; j < end; j++) {
        int2  e  = g_edge[j];
        float cf = __int_as_float(e.y);
        float4 v = *(const float4*)&T[e.x * 4];
        acc.x += v.x * cf; acc.y += v.y * cf;
        acc.z += v.z * cf; acc.w += v.w * cf;
    }
    *(float4*)&O[node * 4] = acc;
}

// ------------------------- launch --------------------------------------------
extern "C" void kernel_launch(void* const* d_in, const int* in_sizes, int n_in,
                              void* d_out, int out_size) {
    const float* x   = (const float*)d_in[0];
    const int*   ei  = (const int*)d_in[1];      // int32 (JAX default int)
    const float* W1  = (const float*)d_in[2];
    const float* b1  = (const float*)d_in[3];
    const float* g1  = (const float*)d_in[4];
    const float* be1 = (const float*)d_in[5];
    const float* W2  = (const float*)d_in[6];
    const float* b2  = (const float*)d_in[7];
    const float* g2  = (const float*)d_in[8];
    const float* be2 = (const float*)d_in[9];
    const float* W3  = (const float*)d_in[10];
    const float* b3  = (const float*)d_in[11];
    float* out = (float*)d_out;

    float *bufA, *bufB, *st1, *st2;
    cudaGetSymbolAddress((void**)&bufA, g_bufA);
    cudaGetSymbolAddress((void**)&bufB, g_bufB);
    cudaGetSymbolAddress((void**)&st1,  g_stats1);
    cudaGetSymbolAddress((void**)&st2,  g_stats2);

    const int TB = 256;
    const int gN   = (N_NODES + TB - 1) / TB;          // 391
    const int gE   = (N_EDGES + TB - 1) / TB;          // 6250
    const int gM32 = N_NODES / 32;                     // 3125
    const int gM64 = (N_NODES + 63) / 64;              // 1563

    // graph prep: degrees, dinv, CSR build (+ zero BN stat accumulators)
    k_zero_cnt<<<gN, TB>>>();
    k_count<<<gE, TB>>>(ei);
    k_dinv<<<gN, TB>>>();
    k_scan1<<<SCAN_NB, SCAN_BS>>>();
    k_scan2<<<1, 256>>>();
    k_scan3<<<gN, TB>>>();
    k_fill<<<gE, TB>>>(ei);

    // layer 1: t1 = x @ W1 ; h1 = aggregate(t1) (+BN1 stats)
    k_gemm_n64<IN_F, false><<<gM32, TB>>>(x, W1, bufA, nullptr, nullptr, nullptr);
    k_gather64<<<GATHER_GRID, TB>>>(bufA, b1, bufB, st1);

    // layer 2: t2 = relu(bn1(h1)) @ W2 ; h2 = aggregate(t2) (+BN2 stats)
    k_gemm_n64<HID, true><<<gM32, TB>>>(bufB, W2, bufA, st1, g1, be1);
    k_gather64<<<GATHER_GRID, TB>>>(bufA, b2, bufB, st2);

    // layer 3: t3 = relu(bn2(h2)) @ W3 ; out = aggregate(t3)
    k_gemm_n4<<<gM64, TB>>>(bufB, W3, bufA, st2, g2, be2);
    k_gather4<<<gN, TB>>>(bufA, b3, out);
}